// round 3
// baseline (speedup 1.0000x reference)
#include <cuda_runtime.h>
#include <cuda_bf16.h>
#include <math.h>
#include <stdint.h>

#define BB   16
#define CC   64
#define NP   128
#define DD   128
#define HT   4
#define DH   32
#define HS   4
#define FF   128
#define DK   64
#define NTOK (BB*CC*NP)      // 131072
#define NSEQ (BB*CC)         // 1024
#define GAT_NEG -1e30f

// ---------------- scratch ----------------------------------------------------
__device__ float g_qkv[(size_t)NTOK*3*DD];
__device__ float g_o[NTOK*DD];
__device__ float g_x[NTOK*DD];
__device__ float g_Htemp[NTOK*DD];
__device__ float g_xh[(size_t)NTOK*HS*FF];
__device__ float g_Hs[NSEQ*DD];
__device__ float g_q2[NSEQ*DK];
__device__ float g_k2[NSEQ*DK];
__device__ float g_mask[BB*CC*CC];

// ---------------- helpers ----------------------------------------------------
__device__ __forceinline__ float to_tf32(float x) {
    asm("cvt.rna.tf32.f32 %0, %1;" : "=f"(x) : "f"(x));
    return x;
}
__device__ __forceinline__ void mma8(float c[4], const uint32_t a[4],
                                     uint32_t b0, uint32_t b1) {
    asm volatile(
        "mma.sync.aligned.m16n8k8.row.col.f32.tf32.tf32.f32 "
        "{%0,%1,%2,%3}, {%4,%5,%6,%7}, {%8,%9}, {%0,%1,%2,%3};"
        : "+f"(c[0]), "+f"(c[1]), "+f"(c[2]), "+f"(c[3])
        : "r"(a[0]), "r"(a[1]), "r"(a[2]), "r"(a[3]), "r"(b0), "r"(b1));
}

// ================= K=128 tensor-core GEMM, full tiles resident ===============
// out[M,N] = op(A) @ W^T (+bias)(+res). op = optional row-LN on A (K==D==128).
// 256 threads, 8 warps as 4(m)x2(n), warp tile 32x64. smem: A[128][132]+B[128][132].
#define STRD 132
__global__ void __launch_bounds__(256, 1)
k_mma128(const float* __restrict__ A, const float* __restrict__ W,
         const float* __restrict__ bias, const float* __restrict__ res,
         float* __restrict__ out, int N,
         const float* __restrict__ lng, const float* __restrict__ lnb,
         int relu)
{
    extern __shared__ float sm[];
    float* As = sm;                 // 128*132
    float* Bs = sm + 128*STRD;      // 128*132
    int tid  = threadIdx.x;
    int warp = tid >> 5, lane = tid & 31;
    int wm = warp >> 1, wn = warp & 1;
    int g = lane >> 2, t = lane & 3;
    int m0 = blockIdx.y * 128;
    int n0 = blockIdx.x * 128;

    // load tiles (raw A if LN, else tf32 immediately)
    #pragma unroll
    for (int i = 0; i < 16; i++) {
        int idx = tid + i * 256;
        int r = idx >> 5, c4 = (idx & 31) << 2;
        float4 a4 = *(const float4*)(A + (size_t)(m0 + r) * DD + c4);
        float4 w4 = *(const float4*)(W + (size_t)(n0 + r) * DD + c4);
        if (!lng) a4 = make_float4(to_tf32(a4.x), to_tf32(a4.y), to_tf32(a4.z), to_tf32(a4.w));
        *(float4*)&As[r*STRD + c4] = a4;
        *(float4*)&Bs[r*STRD + c4] = make_float4(to_tf32(w4.x), to_tf32(w4.y), to_tf32(w4.z), to_tf32(w4.w));
    }
    __syncthreads();

    if (lng) {   // row LayerNorm on A tile: warp w handles rows w, w+8, ...
        float4 g4 = ((const float4*)lng)[lane];
        float4 b4 = ((const float4*)lnb)[lane];
        for (int r = warp; r < 128; r += 8) {
            float4 v = *(float4*)&As[r*STRD + lane*4];
            float s = v.x + v.y + v.z + v.w;
            #pragma unroll
            for (int o = 16; o; o >>= 1) s += __shfl_xor_sync(0xffffffffu, s, o);
            float mean = s * (1.f/128.f);
            float dx=v.x-mean, dy=v.y-mean, dz=v.z-mean, dw=v.w-mean;
            float q = dx*dx+dy*dy+dz*dz+dw*dw;
            #pragma unroll
            for (int o = 16; o; o >>= 1) q += __shfl_xor_sync(0xffffffffu, q, o);
            float inv = rsqrtf(q * (1.f/128.f) + 1e-5f);
            float4 ov;
            ov.x = to_tf32(dx*inv*g4.x + b4.x); ov.y = to_tf32(dy*inv*g4.y + b4.y);
            ov.z = to_tf32(dz*inv*g4.z + b4.z); ov.w = to_tf32(dw*inv*g4.w + b4.w);
            *(float4*)&As[r*STRD + lane*4] = ov;
        }
        __syncthreads();
    }

    float acc[2][8][4] = {};
    #pragma unroll
    for (int kk = 0; kk < 128; kk += 8) {
        uint32_t afrag[2][4];
        #pragma unroll
        for (int mi = 0; mi < 2; mi++) {
            int r = wm * 32 + mi * 16;
            afrag[mi][0] = __float_as_uint(As[(r + g    )*STRD + kk + t    ]);
            afrag[mi][1] = __float_as_uint(As[(r + g + 8)*STRD + kk + t    ]);
            afrag[mi][2] = __float_as_uint(As[(r + g    )*STRD + kk + t + 4]);
            afrag[mi][3] = __float_as_uint(As[(r + g + 8)*STRD + kk + t + 4]);
        }
        #pragma unroll
        for (int ni = 0; ni < 8; ni++) {
            int c = wn * 64 + ni * 8;
            uint32_t b0 = __float_as_uint(Bs[(c + g)*STRD + kk + t    ]);
            uint32_t b1 = __float_as_uint(Bs[(c + g)*STRD + kk + t + 4]);
            mma8(acc[0][ni], afrag[0], b0, b1);
            mma8(acc[1][ni], afrag[1], b0, b1);
        }
    }

    #pragma unroll
    for (int mi = 0; mi < 2; mi++) {
        #pragma unroll
        for (int ni = 0; ni < 8; ni++) {
            int r = m0 + wm * 32 + mi * 16 + g;
            int c = n0 + wn * 64 + ni * 8 + 2 * t;
            float bv0 = bias ? bias[c]     : 0.f;
            float bv1 = bias ? bias[c + 1] : 0.f;
            #pragma unroll
            for (int half = 0; half < 2; half++) {
                int row = r + half * 8;
                float v0 = acc[mi][ni][half*2 + 0] + bv0;
                float v1 = acc[mi][ni][half*2 + 1] + bv1;
                if (relu) { v0 = fmaxf(v0, 0.f); v1 = fmaxf(v1, 0.f); }
                if (res) {
                    const float2 rr = *(const float2*)(res + (size_t)row * N + c);
                    v0 += rr.x; v1 += rr.y;
                }
                *(float2*)(out + (size_t)row * N + c) = make_float2(v0, v1);
            }
        }
    }
}

// ================= fused FFN: ln2 -> ff1+relu -> ff2 -> +x1+x0 -> tnorm ======
// 64-row tile per CTA. 8 warps as 2(m)x4(n), warp tile 32x32.
// smem: As[64][132] (ln'd x1, tf32), Ws[128][132], Ms[64][132].
__global__ void __launch_bounds__(256, 1)
k_ffn(const float* __restrict__ x1, const float* __restrict__ x0,
      const float* __restrict__ w1, const float* __restrict__ b1,
      const float* __restrict__ w2, const float* __restrict__ b2,
      const float* __restrict__ ln2g, const float* __restrict__ ln2b,
      const float* __restrict__ tg, const float* __restrict__ tb,
      float* __restrict__ out)
{
    extern __shared__ float sm[];
    float* As = sm;                  // 64*132
    float* Ws = sm + 64*STRD;        // 128*132
    float* Ms = sm + 192*STRD;       // 64*132
    int tid  = threadIdx.x;
    int warp = tid >> 5, lane = tid & 31;
    int wm = warp >> 2, wn = warp & 3;       // 2 x 4
    int g = lane >> 2, t = lane & 3;
    int m0 = blockIdx.x * 64;

    // ---- load x1 tile, LN2 -> As (tf32) ----
    {
        float4 g4 = ((const float4*)ln2g)[lane];
        float4 b4 = ((const float4*)ln2b)[lane];
        for (int r = warp; r < 64; r += 8) {
            float4 v = ((const float4*)(x1 + (size_t)(m0 + r) * DD))[lane];
            float s = v.x + v.y + v.z + v.w;
            #pragma unroll
            for (int o = 16; o; o >>= 1) s += __shfl_xor_sync(0xffffffffu, s, o);
            float mean = s * (1.f/128.f);
            float dx=v.x-mean, dy=v.y-mean, dz=v.z-mean, dw=v.w-mean;
            float q = dx*dx+dy*dy+dz*dz+dw*dw;
            #pragma unroll
            for (int o = 16; o; o >>= 1) q += __shfl_xor_sync(0xffffffffu, q, o);
            float inv = rsqrtf(q * (1.f/128.f) + 1e-5f);
            float4 ov;
            ov.x = to_tf32(dx*inv*g4.x + b4.x); ov.y = to_tf32(dy*inv*g4.y + b4.y);
            ov.z = to_tf32(dz*inv*g4.z + b4.z); ov.w = to_tf32(dw*inv*g4.w + b4.w);
            *(float4*)&As[r*STRD + lane*4] = ov;
        }
    }

    float acc2[2][4][4] = {};

    for (int n0 = 0; n0 < 512; n0 += 128) {
        // ---- load W1 rows n0..n0+127 ----
        __syncthreads();
        #pragma unroll
        for (int i = 0; i < 16; i++) {
            int idx = tid + i * 256;
            int r = idx >> 5, c4 = (idx & 31) << 2;
            float4 w4 = *(const float4*)(w1 + (size_t)(n0 + r) * DD + c4);
            *(float4*)&Ws[r*STRD + c4] = make_float4(to_tf32(w4.x), to_tf32(w4.y), to_tf32(w4.z), to_tf32(w4.w));
        }
        __syncthreads();

        // ---- mid = relu(As @ W1tile^T + b1) ----
        float acc1[2][4][4] = {};
        #pragma unroll
        for (int kk = 0; kk < 128; kk += 8) {
            uint32_t afrag[2][4];
            #pragma unroll
            for (int mi = 0; mi < 2; mi++) {
                int r = wm * 32 + mi * 16;
                afrag[mi][0] = __float_as_uint(As[(r + g    )*STRD + kk + t    ]);
                afrag[mi][1] = __float_as_uint(As[(r + g + 8)*STRD + kk + t    ]);
                afrag[mi][2] = __float_as_uint(As[(r + g    )*STRD + kk + t + 4]);
                afrag[mi][3] = __float_as_uint(As[(r + g + 8)*STRD + kk + t + 4]);
            }
            #pragma unroll
            for (int ni = 0; ni < 4; ni++) {
                int c = wn * 32 + ni * 8;
                uint32_t b0 = __float_as_uint(Ws[(c + g)*STRD + kk + t    ]);
                uint32_t b1v= __float_as_uint(Ws[(c + g)*STRD + kk + t + 4]);
                mma8(acc1[0][ni], afrag[0], b0, b1v);
                mma8(acc1[1][ni], afrag[1], b0, b1v);
            }
        }
        // store relu'd tf32 mid to Ms
        #pragma unroll
        for (int mi = 0; mi < 2; mi++) {
            #pragma unroll
            for (int ni = 0; ni < 4; ni++) {
                int r = wm * 32 + mi * 16 + g;
                int c = wn * 32 + ni * 8 + 2 * t;
                float bb0 = b1[n0 + c], bb1 = b1[n0 + c + 1];
                #pragma unroll
                for (int half = 0; half < 2; half++) {
                    int row = r + half * 8;
                    Ms[row*STRD + c    ] = to_tf32(fmaxf(acc1[mi][ni][half*2+0] + bb0, 0.f));
                    Ms[row*STRD + c + 1] = to_tf32(fmaxf(acc1[mi][ni][half*2+1] + bb1, 0.f));
                }
            }
        }
        __syncthreads();

        // ---- load W2 slice: rows n=0..127 (out cols), cols n0..n0+127 of K=512
        #pragma unroll
        for (int i = 0; i < 16; i++) {
            int idx = tid + i * 256;
            int r = idx >> 5, c4 = (idx & 31) << 2;
            float4 w4 = *(const float4*)(w2 + (size_t)r * 512 + n0 + c4);
            *(float4*)&Ws[r*STRD + c4] = make_float4(to_tf32(w4.x), to_tf32(w4.y), to_tf32(w4.z), to_tf32(w4.w));
        }
        __syncthreads();

        // ---- acc2 += Ms @ W2slice^T ----
        #pragma unroll
        for (int kk = 0; kk < 128; kk += 8) {
            uint32_t afrag[2][4];
            #pragma unroll
            for (int mi = 0; mi < 2; mi++) {
                int r = wm * 32 + mi * 16;
                afrag[mi][0] = __float_as_uint(Ms[(r + g    )*STRD + kk + t    ]);
                afrag[mi][1] = __float_as_uint(Ms[(r + g + 8)*STRD + kk + t    ]);
                afrag[mi][2] = __float_as_uint(Ms[(r + g    )*STRD + kk + t + 4]);
                afrag[mi][3] = __float_as_uint(Ms[(r + g + 8)*STRD + kk + t + 4]);
            }
            #pragma unroll
            for (int ni = 0; ni < 4; ni++) {
                int c = wn * 32 + ni * 8;
                uint32_t b0 = __float_as_uint(Ws[(c + g)*STRD + kk + t    ]);
                uint32_t b1v= __float_as_uint(Ws[(c + g)*STRD + kk + t + 4]);
                mma8(acc2[0][ni], afrag[0], b0, b1v);
                mma8(acc2[1][ni], afrag[1], b0, b1v);
            }
        }
    }

    // ---- v = acc2 + b2 + x1 + x0 -> Ms; then row-LN (tnorm) -> out ----
    __syncthreads();
    #pragma unroll
    for (int mi = 0; mi < 2; mi++) {
        #pragma unroll
        for (int ni = 0; ni < 4; ni++) {
            int r = wm * 32 + mi * 16 + g;
            int c = wn * 32 + ni * 8 + 2 * t;
            float bb0 = b2[c], bb1 = b2[c + 1];
            #pragma unroll
            for (int half = 0; half < 2; half++) {
                int row = r + half * 8;
                const float2 r1 = *(const float2*)(x1 + (size_t)(m0 + row) * DD + c);
                const float2 r0 = *(const float2*)(x0 + (size_t)(m0 + row) * DD + c);
                Ms[row*STRD + c    ] = acc2[mi][ni][half*2+0] + bb0 + r1.x + r0.x;
                Ms[row*STRD + c + 1] = acc2[mi][ni][half*2+1] + bb1 + r1.y + r0.y;
            }
        }
    }
    __syncthreads();
    {
        float4 g4 = ((const float4*)tg)[lane];
        float4 b4 = ((const float4*)tb)[lane];
        for (int r = warp; r < 64; r += 8) {
            float4 v = *(float4*)&Ms[r*STRD + lane*4];
            float s = v.x + v.y + v.z + v.w;
            #pragma unroll
            for (int o = 16; o; o >>= 1) s += __shfl_xor_sync(0xffffffffu, s, o);
            float mean = s * (1.f/128.f);
            float dx=v.x-mean, dy=v.y-mean, dz=v.z-mean, dw=v.w-mean;
            float q = dx*dx+dy*dy+dz*dz+dw*dw;
            #pragma unroll
            for (int o = 16; o; o >>= 1) q += __shfl_xor_sync(0xffffffffu, q, o);
            float inv = rsqrtf(q * (1.f/128.f) + 1e-5f);
            float4 ov;
            ov.x = dx*inv*g4.x + b4.x; ov.y = dy*inv*g4.y + b4.y;
            ov.z = dz*inv*g4.z + b4.z; ov.w = dw*inv*g4.w + b4.w;
            ((float4*)(out + (size_t)(m0 + r) * DD))[lane] = ov;
        }
    }
}

// ---------------- temporal attention: CTA per (seq, head) --------------------
__global__ void k_attn()
{
    extern __shared__ float sm[];
    float* Ks = sm;
    float* Vs = sm + 4096;
    float* S  = sm + 8192;   // stride 129
    int n = blockIdx.x >> 2, h = blockIdx.x & 3;
    int i = threadIdx.x;
    const float* base = g_qkv + (size_t)n * NP * 3 * DD;
    for (int idx = i; idx < NP*DH; idx += 128) {
        int j = idx >> 5, d = idx & 31;
        Ks[idx] = base[j*384 + 128 + h*32 + d];
        Vs[idx] = base[j*384 + 256 + h*32 + d];
    }
    float4 qr[8];
    const float4* qp = (const float4*)(base + (size_t)i*384 + h*32);
    #pragma unroll
    for (int d = 0; d < 8; d++) qr[d] = qp[d];
    __syncthreads();
    const float scale = 0.17677669529663687f;
    float mx = -INFINITY;
    for (int j = 0; j < NP; j++) {
        const float4* kp = (const float4*)(Ks + j*32);
        float a = 0.f;
        #pragma unroll
        for (int d = 0; d < 8; d++) {
            float4 kv = kp[d];
            a += qr[d].x*kv.x + qr[d].y*kv.y + qr[d].z*kv.z + qr[d].w*kv.w;
        }
        a *= scale;
        S[i*129 + j] = a;
        mx = fmaxf(mx, a);
    }
    float ssum = 0.f;
    for (int j = 0; j < NP; j++) {
        float e = expf(S[i*129 + j] - mx);
        S[i*129 + j] = e;
        ssum += e;
    }
    float4 o4[8] = {};
    for (int j = 0; j < NP; j++) {
        float p = S[i*129 + j];
        const float4* vp = (const float4*)(Vs + j*32);
        #pragma unroll
        for (int d = 0; d < 8; d++) {
            float4 vv = vp[d];
            o4[d].x += p*vv.x; o4[d].y += p*vv.y; o4[d].z += p*vv.z; o4[d].w += p*vv.w;
        }
    }
    float inv = 1.f / ssum;
    float4* op = (float4*)(g_o + (size_t)(n*NP + i)*DD + h*32);
    #pragma unroll
    for (int d = 0; d < 8; d++) {
        float4 v = o4[d];
        v.x *= inv; v.y *= inv; v.z *= inv; v.w *= inv;
        op[d] = v;
    }
}

// ---------------- mean over Np -----------------------------------------------
__global__ void k_mean()
{
    int n = blockIdx.x, d = threadIdx.x;
    float s = 0.f;
    for (int p = 0; p < NP; p++) s += g_Htemp[((size_t)n*NP + p)*DD + d];
    g_Hs[n*DD + d] = s * (1.f/128.f);
}

// ---------------- small SIMT GEMM (q2/k2) ------------------------------------
#define BM 64
#define BN 64
#define BK 16
__global__ void k_gemm(const float* __restrict__ A, const float* __restrict__ W,
                       const float* __restrict__ bias, float* __restrict__ out,
                       int M, int N, int K)
{
    __shared__ float As[BK][BM];
    __shared__ float Bs[BK][BN];
    int tid = threadIdx.x;
    int tx = tid & 15, ty = tid >> 4;
    int m0 = blockIdx.y * BM, n0 = blockIdx.x * BN;
    int lr = tid >> 2;
    int lk = (tid & 3) * 4;
    float acc[4][4] = {};
    for (int k0 = 0; k0 < K; k0 += BK) {
        float4 a4 = *(const float4*)(A + (size_t)(m0 + lr) * K + k0 + lk);
        float4 b4 = *(const float4*)(W + (size_t)(n0 + lr) * K + k0 + lk);
        As[lk+0][lr] = a4.x; As[lk+1][lr] = a4.y; As[lk+2][lr] = a4.z; As[lk+3][lr] = a4.w;
        Bs[lk+0][lr] = b4.x; Bs[lk+1][lr] = b4.y; Bs[lk+2][lr] = b4.z; Bs[lk+3][lr] = b4.w;
        __syncthreads();
        #pragma unroll
        for (int k = 0; k < BK; k++) {
            float4 ra = *(const float4*)&As[k][ty*4];
            float4 rb = *(const float4*)&Bs[k][tx*4];
            float av[4] = {ra.x, ra.y, ra.z, ra.w};
            float bv[4] = {rb.x, rb.y, rb.z, rb.w};
            #pragma unroll
            for (int i = 0; i < 4; i++)
                #pragma unroll
                for (int j = 0; j < 4; j++)
                    acc[i][j] += av[i] * bv[j];
        }
        __syncthreads();
    }
    #pragma unroll
    for (int i = 0; i < 4; i++) {
        int m = m0 + ty*4 + i;
        #pragma unroll
        for (int j = 0; j < 4; j++) {
            int n = n0 + tx*4 + j;
            out[(size_t)m * N + n] = acc[i][j] + bias[n];
        }
    }
}

// ---------------- graph adjacency --------------------------------------------
__global__ void k_graph(const float* __restrict__ adj)
{
    __shared__ float k2s[CC*DK];
    __shared__ float Amat[CC*65];
    int b = blockIdx.x, c = threadIdx.x;
    for (int idx = c; idx < CC*DK; idx += 64) k2s[idx] = g_k2[(size_t)b*CC*DK + idx];
    __syncthreads();
    float qreg[DK];
    #pragma unroll
    for (int d = 0; d < DK; d++) qreg[d] = g_q2[(size_t)b*CC*DK + c*DK + d];
    for (int e = 0; e < CC; e++) {
        float a = 0.f;
        #pragma unroll
        for (int d = 0; d < DK; d++) a += qreg[d] * k2s[e*DK + d];
        Amat[c*65 + e] = tanhf(a * 0.125f) + adj[c*CC + e];
    }
    for (int e = 0; e < CC; e++) g_mask[(size_t)b*CC*CC + c*CC + e] = 0.f;
    for (int kk = 0; kk < 8; kk++) {
        float best = -INFINITY; int bi = 0;
        for (int e = 0; e < CC; e++) {
            float v = Amat[c*65 + e];
            if (v > best) { best = v; bi = e; }
        }
        if (bi != c && best != 0.f) g_mask[(size_t)b*CC*CC + c*CC + bi] = 1.f;
        Amat[c*65 + bi] = -INFINITY;
    }
}

// ---------------- fused GAT + snorm LN: CTA per (b, p) ------------------------
__global__ void k_gat(const float* __restrict__ attsrc, const float* __restrict__ attdst,
                      const float* __restrict__ gbias, const float* __restrict__ sg,
                      const float* __restrict__ sb, float* __restrict__ out)
{
    extern __shared__ float sm[];
    float* Xh  = sm;               // 8192
    float* Aw  = sm + 8192;        // 4160 (stride 65)
    float* Asv = sm + 12352;       // 64
    float* Adv = sm + 12416;       // 64
    int b = blockIdx.x >> 7, p = blockIdx.x & 127;
    int tid = threadIdx.x, w = tid >> 5, lane = tid & 31;

    float acc[8][4] = {};
    for (int h = 0; h < HS; h++) {
        __syncthreads();
        for (int idx = tid; idx < CC*FF; idx += 256) {
            int s = idx >> 7, f = idx & 127;
            Xh[idx] = g_xh[(size_t)(((b*CC + s)*NP + p))*(HS*FF) + h*FF + f];
        }
        __syncthreads();

        for (int s = w; s < CC; s += 8) {
            float vs = 0.f, vd = 0.f;
            #pragma unroll
            for (int j = 0; j < 4; j++) {
                int f = lane + 32*j;
                float xv = Xh[s*FF + f];
                vs += xv * attsrc[h*FF + f];
                vd += xv * attdst[h*FF + f];
            }
            #pragma unroll
            for (int o = 16; o; o >>= 1) {
                vs += __shfl_xor_sync(0xffffffffu, vs, o);
                vd += __shfl_xor_sync(0xffffffffu, vd, o);
            }
            if (lane == 0) { Asv[s] = vs; Adv[s] = vd; }
        }
        __syncthreads();

        #pragma unroll
        for (int i = 0; i < 8; i++) {
            int t = w*8 + i;
            float adt = Adv[t];
            float m0 = g_mask[(size_t)b*CC*CC + lane*CC + t];
            float m1 = g_mask[(size_t)b*CC*CC + (lane+32)*CC + t];
            float e0 = Asv[lane]      + adt; e0 = e0 > 0.f ? e0 : 0.2f*e0;
            float e1 = Asv[lane + 32] + adt; e1 = e1 > 0.f ? e1 : 0.2f*e1;
            float me = fmaxf(m0 > 0.5f ? e0 : GAT_NEG, m1 > 0.5f ? e1 : GAT_NEG);
            #pragma unroll
            for (int o = 16; o; o >>= 1) me = fmaxf(me, __shfl_xor_sync(0xffffffffu, me, o));
            float w0 = (m0 > 0.5f) ? expf(e0 - me) : 0.f;
            float w1 = (m1 > 0.5f) ? expf(e1 - me) : 0.f;
            float ws = w0 + w1;
            #pragma unroll
            for (int o = 16; o; o >>= 1) ws += __shfl_xor_sync(0xffffffffu, ws, o);
            float inv = ws > 0.f ? 1.f / ws : 0.f;
            Aw[lane*65 + t]      = w0 * inv;
            Aw[(lane+32)*65 + t] = w1 * inv;
        }
        __syncthreads();

        for (int s = 0; s < CC; s++) {
            float xv[4];
            #pragma unroll
            for (int j = 0; j < 4; j++) xv[j] = Xh[s*FF + lane + 32*j];
            #pragma unroll
            for (int i = 0; i < 8; i++) {
                float a = Aw[s*65 + w*8 + i];
                #pragma unroll
                for (int j = 0; j < 4; j++) acc[i][j] += a * xv[j];
            }
        }
    }

    #pragma unroll
    for (int i = 0; i < 8; i++) {
        int t = w*8 + i;
        const float* hrow = &g_Htemp[(((size_t)(b*CC + t))*NP + p)*DD];
        float v[4]; float s1 = 0.f;
        #pragma unroll
        for (int j = 0; j < 4; j++) {
            int f = lane + 32*j;
            v[j] = acc[i][j]*0.25f + gbias[f] + hrow[f];
            s1 += v[j];
        }
        #pragma unroll
        for (int o = 16; o; o >>= 1) s1 += __shfl_xor_sync(0xffffffffu, s1, o);
        float mean = s1 * (1.f/128.f);
        float s2 = 0.f;
        #pragma unroll
        for (int j = 0; j < 4; j++) { float d = v[j] - mean; s2 += d*d; }
        #pragma unroll
        for (int o = 16; o; o >>= 1) s2 += __shfl_xor_sync(0xffffffffu, s2, o);
        float inv = rsqrtf(s2 * (1.f/128.f) + 1e-5f);
        #pragma unroll
        for (int j = 0; j < 4; j++) {
            int f = lane + 32*j;
            out[(((size_t)(b*CC + t))*NP + p)*DD + f] = (v[j] - mean)*inv*sg[f] + sb[f];
        }
    }
}

// ---------------- host launch -------------------------------------------------
extern "C" void kernel_launch(void* const* d_in, const int* in_sizes, int n_in,
                              void* d_out, int out_size)
{
    const float* H_in      = (const float*)d_in[0];
    const float* static_adj= (const float*)d_in[1];
    const float* attn_in_w = (const float*)d_in[2];
    const float* attn_in_b = (const float*)d_in[3];
    const float* attn_out_w= (const float*)d_in[4];
    const float* attn_out_b= (const float*)d_in[5];
    const float* ln1_g     = (const float*)d_in[6];
    const float* ln1_b     = (const float*)d_in[7];
    const float* ln2_g     = (const float*)d_in[8];
    const float* ln2_b     = (const float*)d_in[9];
    const float* ff1_w     = (const float*)d_in[10];
    const float* ff1_b     = (const float*)d_in[11];
    const float* ff2_w     = (const float*)d_in[12];
    const float* ff2_b     = (const float*)d_in[13];
    const float* tnorm_g   = (const float*)d_in[14];
    const float* tnorm_b   = (const float*)d_in[15];
    const float* q_w       = (const float*)d_in[16];
    const float* q_b       = (const float*)d_in[17];
    const float* k_w       = (const float*)d_in[18];
    const float* k_b       = (const float*)d_in[19];
    const float* gat_w     = (const float*)d_in[20];
    const float* gat_att_src = (const float*)d_in[21];
    const float* gat_att_dst = (const float*)d_in[22];
    const float* gat_bias  = (const float*)d_in[23];
    const float* snorm_g   = (const float*)d_in[24];
    const float* snorm_b   = (const float*)d_in[25];

    float *qkv_, *o_, *x_, *Htemp_, *xh_, *Hs_, *q2_, *k2_;
    cudaGetSymbolAddress((void**)&qkv_,   g_qkv);
    cudaGetSymbolAddress((void**)&o_,     g_o);
    cudaGetSymbolAddress((void**)&x_,     g_x);
    cudaGetSymbolAddress((void**)&Htemp_, g_Htemp);
    cudaGetSymbolAddress((void**)&xh_,    g_xh);
    cudaGetSymbolAddress((void**)&Hs_,    g_Hs);
    cudaGetSymbolAddress((void**)&q2_,    g_q2);
    cudaGetSymbolAddress((void**)&k2_,    g_k2);

    const int mma_smem  = 2 * 128 * STRD * 4;          // 135168
    const int ffn_smem  = 256 * STRD * 4;              // 135168
    const int attn_smem = (4096 + 4096 + 128*129) * 4; // 98816
    const int gat_smem  = 12480 * 4;                   // 49920
    cudaFuncSetAttribute(k_mma128, cudaFuncAttributeMaxDynamicSharedMemorySize, mma_smem);
    cudaFuncSetAttribute(k_ffn,  cudaFuncAttributeMaxDynamicSharedMemorySize, ffn_smem);
    cudaFuncSetAttribute(k_attn, cudaFuncAttributeMaxDynamicSharedMemorySize, attn_smem);
    cudaFuncSetAttribute(k_gat,  cudaFuncAttributeMaxDynamicSharedMemorySize, gat_smem);

    // 1) qkv = ln1(x0) @ Wqkv^T + b   (LN fused)
    k_mma128<<<dim3(3, NTOK/128), 256, mma_smem>>>(H_in, attn_in_w, attn_in_b, nullptr,
                                                   qkv_, 384, ln1_g, ln1_b, 0);
    // 2) temporal attention
    k_attn<<<NSEQ*HT, 128, attn_smem>>>();
    // 3) x1 = x0 + o @ Wout^T + b
    k_mma128<<<dim3(1, NTOK/128), 256, mma_smem>>>(o_, attn_out_w, attn_out_b, H_in,
                                                   x_, 128, nullptr, nullptr, 0);
    // 4) fused FFN + tnorm -> H_temp
    k_ffn<<<NTOK/64, 256, ffn_smem>>>(x_, H_in, ff1_w, ff1_b, ff2_w, ff2_b,
                                      ln2_g, ln2_b, tnorm_g, tnorm_b, Htemp_);
    // 5) xh = H_temp @ gat_w^T
    k_mma128<<<dim3(4, NTOK/128), 256, mma_smem>>>(Htemp_, gat_w, nullptr, nullptr,
                                                   xh_, 512, nullptr, nullptr, 0);
    // 6) Hs = mean_p(H_temp)
    k_mean<<<NSEQ, 128>>>();
    // 7) q2, k2
    k_gemm<<<dim3(1, NSEQ/BM), 256>>>(Hs_, q_w, q_b, q2_, NSEQ, 64, 128);
    k_gemm<<<dim3(1, NSEQ/BM), 256>>>(Hs_, k_w, k_b, k2_, NSEQ, 64, 128);
    // 8) adjacency / top-k / mask
    k_graph<<<BB, 64>>>(static_adj);
    // 9) fused GAT + snorm LN -> output
    k_gat<<<BB*NP, 256, gat_smem>>>(gat_att_src, gat_att_dst, gat_bias,
                                    snorm_g, snorm_b, (float*)d_out);
}

// round 4
// speedup vs baseline: 1.2345x; 1.2345x over previous
#include <cuda_runtime.h>
#include <cuda_bf16.h>
#include <math.h>
#include <stdint.h>

#define BB   16
#define CC   64
#define NP   128
#define DD   128
#define HT   4
#define DH   32
#define HS   4
#define FF   128
#define DK   64
#define NTOK (BB*CC*NP)      // 131072
#define NSEQ (BB*CC)         // 1024
#define GAT_NEG -1e30f

// ---------------- scratch ----------------------------------------------------
__device__ float g_h[NTOK*DD];
__device__ float g_qkv[(size_t)NTOK*3*DD];
__device__ float g_o[NTOK*DD];
__device__ float g_x[NTOK*DD];
__device__ float g_ff[(size_t)NTOK*4*DD];
__device__ float g_Htemp[NTOK*DD];
__device__ float g_xh[(size_t)NTOK*HS*FF];
__device__ float g_Hs[NSEQ*DD];
__device__ float g_q2[NSEQ*DK];
__device__ float g_k2[NSEQ*DK];
__device__ float g_mask[BB*CC*CC];

// ---------------- helpers ----------------------------------------------------
__device__ __forceinline__ float to_tf32(float x) {
    asm("cvt.rna.tf32.f32 %0, %1;" : "=f"(x) : "f"(x));
    return x;
}
__device__ __forceinline__ void mma8(float c[4], const uint32_t a[4],
                                     uint32_t b0, uint32_t b1) {
    asm volatile(
        "mma.sync.aligned.m16n8k8.row.col.f32.tf32.tf32.f32 "
        "{%0,%1,%2,%3}, {%4,%5,%6,%7}, {%8,%9}, {%0,%1,%2,%3};"
        : "+f"(c[0]), "+f"(c[1]), "+f"(c[2]), "+f"(c[3])
        : "r"(a[0]), "r"(a[1]), "r"(a[2]), "r"(a[3]), "r"(b0), "r"(b1));
}

// ---------------- LayerNorm: warp per row, optional fused add ----------------
__global__ void k_ln(const float* __restrict__ x, const float* __restrict__ add,
                     const float* __restrict__ gw, const float* __restrict__ bw,
                     float* __restrict__ out)
{
    int row  = blockIdx.x * 8 + (threadIdx.x >> 5);
    int lane = threadIdx.x & 31;
    const float4* xp = (const float4*)(x + (size_t)row * DD);
    float4 v = xp[lane];
    if (add) {
        float4 a = ((const float4*)(add + (size_t)row * DD))[lane];
        v.x += a.x; v.y += a.y; v.z += a.z; v.w += a.w;
    }
    float s = v.x + v.y + v.z + v.w;
    #pragma unroll
    for (int o = 16; o; o >>= 1) s += __shfl_xor_sync(0xffffffffu, s, o);
    float mean = s * (1.f/128.f);
    float dx = v.x-mean, dy = v.y-mean, dz = v.z-mean, dw = v.w-mean;
    float q = dx*dx + dy*dy + dz*dz + dw*dw;
    #pragma unroll
    for (int o = 16; o; o >>= 1) q += __shfl_xor_sync(0xffffffffu, q, o);
    float inv = rsqrtf(q * (1.f/128.f) + 1e-5f);
    float4 g4 = ((const float4*)gw)[lane];
    float4 b4 = ((const float4*)bw)[lane];
    float4 o4;
    o4.x = dx*inv*g4.x + b4.x;  o4.y = dy*inv*g4.y + b4.y;
    o4.z = dz*inv*g4.z + b4.z;  o4.w = dw*inv*g4.w + b4.w;
    ((float4*)(out + (size_t)row * DD))[lane] = o4;
}

// ---------------- tf32 tensor-core GEMM (R2-proven) --------------------------
#define TBM 128
#define TBN 128
#define TBK 32
#define TPAD 4
__global__ void k_mma(const float* __restrict__ A, const float* __restrict__ W,
                      const float* __restrict__ bias, const float* __restrict__ res,
                      float* __restrict__ out, int M, int N, int K, int relu)
{
    __shared__ float As[TBM][TBK + TPAD];
    __shared__ float Bs[TBN][TBK + TPAD];
    int tid  = threadIdx.x;
    int warp = tid >> 5, lane = tid & 31;
    int wm = warp >> 1, wn = warp & 1;
    int g = lane >> 2, t = lane & 3;
    int m0 = blockIdx.y * TBM;
    int n0 = blockIdx.x * TBN;

    float acc[2][8][4] = {};

    for (int k0 = 0; k0 < K; k0 += TBK) {
        #pragma unroll
        for (int i = 0; i < 4; i++) {
            int idx = tid + i * 256;
            int r = idx >> 3, c4 = (idx & 7) << 2;
            float4 a4 = *(const float4*)(A + (size_t)(m0 + r) * K + k0 + c4);
            float4 w4 = *(const float4*)(W + (size_t)(n0 + r) * K + k0 + c4);
            *(float4*)&As[r][c4] = make_float4(to_tf32(a4.x), to_tf32(a4.y), to_tf32(a4.z), to_tf32(a4.w));
            *(float4*)&Bs[r][c4] = make_float4(to_tf32(w4.x), to_tf32(w4.y), to_tf32(w4.z), to_tf32(w4.w));
        }
        __syncthreads();
        #pragma unroll
        for (int kk = 0; kk < TBK; kk += 8) {
            uint32_t afrag[2][4];
            #pragma unroll
            for (int mi = 0; mi < 2; mi++) {
                int r = wm * 32 + mi * 16;
                afrag[mi][0] = __float_as_uint(As[r + g    ][kk + t    ]);
                afrag[mi][1] = __float_as_uint(As[r + g + 8][kk + t    ]);
                afrag[mi][2] = __float_as_uint(As[r + g    ][kk + t + 4]);
                afrag[mi][3] = __float_as_uint(As[r + g + 8][kk + t + 4]);
            }
            #pragma unroll
            for (int ni = 0; ni < 8; ni++) {
                int c = wn * 64 + ni * 8;
                uint32_t b0 = __float_as_uint(Bs[c + g][kk + t    ]);
                uint32_t b1 = __float_as_uint(Bs[c + g][kk + t + 4]);
                mma8(acc[0][ni], afrag[0], b0, b1);
                mma8(acc[1][ni], afrag[1], b0, b1);
            }
        }
        __syncthreads();
    }

    #pragma unroll
    for (int mi = 0; mi < 2; mi++) {
        #pragma unroll
        for (int ni = 0; ni < 8; ni++) {
            int r = m0 + wm * 32 + mi * 16 + g;
            int c = n0 + wn * 64 + ni * 8 + 2 * t;
            float bv0 = bias ? bias[c]     : 0.f;
            float bv1 = bias ? bias[c + 1] : 0.f;
            #pragma unroll
            for (int half = 0; half < 2; half++) {
                int row = r + half * 8;
                float v0 = acc[mi][ni][half*2 + 0] + bv0;
                float v1 = acc[mi][ni][half*2 + 1] + bv1;
                if (relu) { v0 = fmaxf(v0, 0.f); v1 = fmaxf(v1, 0.f); }
                if (res) {
                    const float2 rr = *(const float2*)(res + (size_t)row * N + c);
                    v0 += rr.x; v1 += rr.y;
                }
                *(float2*)(out + (size_t)row * N + c) = make_float2(v0, v1);
            }
        }
    }
}

// ---------------- small SIMT GEMM (q2/k2) ------------------------------------
#define BM 64
#define BN 64
#define BK 16
__global__ void k_gemm(const float* __restrict__ A, const float* __restrict__ W,
                       const float* __restrict__ bias, float* __restrict__ out,
                       int M, int N, int K)
{
    __shared__ float As[BK][BM];
    __shared__ float Bs[BK][BN];
    int tid = threadIdx.x;
    int tx = tid & 15, ty = tid >> 4;
    int m0 = blockIdx.y * BM, n0 = blockIdx.x * BN;
    int lr = tid >> 2;
    int lk = (tid & 3) * 4;
    float acc[4][4] = {};
    for (int k0 = 0; k0 < K; k0 += BK) {
        float4 a4 = *(const float4*)(A + (size_t)(m0 + lr) * K + k0 + lk);
        float4 b4 = *(const float4*)(W + (size_t)(n0 + lr) * K + k0 + lk);
        As[lk+0][lr] = a4.x; As[lk+1][lr] = a4.y; As[lk+2][lr] = a4.z; As[lk+3][lr] = a4.w;
        Bs[lk+0][lr] = b4.x; Bs[lk+1][lr] = b4.y; Bs[lk+2][lr] = b4.z; Bs[lk+3][lr] = b4.w;
        __syncthreads();
        #pragma unroll
        for (int k = 0; k < BK; k++) {
            float4 ra = *(const float4*)&As[k][ty*4];
            float4 rb = *(const float4*)&Bs[k][tx*4];
            float av[4] = {ra.x, ra.y, ra.z, ra.w};
            float bv[4] = {rb.x, rb.y, rb.z, rb.w};
            #pragma unroll
            for (int i = 0; i < 4; i++)
                #pragma unroll
                for (int j = 0; j < 4; j++)
                    acc[i][j] += av[i] * bv[j];
        }
        __syncthreads();
    }
    #pragma unroll
    for (int i = 0; i < 4; i++) {
        int m = m0 + ty*4 + i;
        #pragma unroll
        for (int j = 0; j < 4; j++) {
            int n = n0 + tx*4 + j;
            out[(size_t)m * N + n] = acc[i][j] + bias[n];
        }
    }
}

// ============== tensor-core attention: CTA(128thr) per (seq, head) ===========
// smem union: phase A: Qs[128][36] Ks[128][36]  /  phase B: Ps[128][132]
// plus VT[32][132] (V transposed, d-major)
#define AQS 36
#define APS 132
__global__ void __launch_bounds__(128)
k_attn_mma()
{
    extern __shared__ float sm[];
    float* U  = sm;                   // union region (128*132 floats)
    float* VT = sm + 128*APS;         // 32*132 floats
    float* Qs = U;
    float* Ks = U + 128*AQS;
    float* Ps = U;

    int n = blockIdx.x >> 2, h = blockIdx.x & 3;
    int tid = threadIdx.x;
    int warp = tid >> 5, lane = tid & 31;
    int g = lane >> 2, t = lane & 3;
    int m0 = warp * 32;
    const float* base = g_qkv + (size_t)n * NP * 3 * DD;

    // load Q, K (row-major) and V transposed, all tf32
    for (int idx = tid; idx < NP*DH; idx += 128) {
        int j = idx >> 5, d = idx & 31;
        Qs[j*AQS + d]  = to_tf32(base[j*384 +       h*32 + d]);
        Ks[j*AQS + d]  = to_tf32(base[j*384 + 128 + h*32 + d]);
        VT[d*APS + j]  = to_tf32(base[j*384 + 256 + h*32 + d]);
    }
    __syncthreads();

    // ---- S = Q @ K^T for this warp's 32 rows (full 128 cols in regs) ----
    float s[2][16][4] = {};
    #pragma unroll
    for (int kk = 0; kk < 32; kk += 8) {
        uint32_t afrag[2][4];
        #pragma unroll
        for (int mi = 0; mi < 2; mi++) {
            int r = m0 + mi * 16;
            afrag[mi][0] = __float_as_uint(Qs[(r + g    )*AQS + kk + t    ]);
            afrag[mi][1] = __float_as_uint(Qs[(r + g + 8)*AQS + kk + t    ]);
            afrag[mi][2] = __float_as_uint(Qs[(r + g    )*AQS + kk + t + 4]);
            afrag[mi][3] = __float_as_uint(Qs[(r + g + 8)*AQS + kk + t + 4]);
        }
        #pragma unroll
        for (int ni = 0; ni < 16; ni++) {
            int c = ni * 8;
            uint32_t b0 = __float_as_uint(Ks[(c + g)*AQS + kk + t    ]);
            uint32_t b1 = __float_as_uint(Ks[(c + g)*AQS + kk + t + 4]);
            mma8(s[0][ni], afrag[0], b0, b1);
            mma8(s[1][ni], afrag[1], b0, b1);
        }
    }
    __syncthreads();   // all warps done reading Qs/Ks; U becomes Ps

    // ---- softmax in registers (rows: mi*16+g and +8) ----
    const float scale = 0.17677669529663687f;  // 1/sqrt(32)
    float mx[2][2] = {{-INFINITY,-INFINITY},{-INFINITY,-INFINITY}};
    #pragma unroll
    for (int mi = 0; mi < 2; mi++)
        #pragma unroll
        for (int ni = 0; ni < 16; ni++) {
            #pragma unroll
            for (int q = 0; q < 4; q++) s[mi][ni][q] *= scale;
            mx[mi][0] = fmaxf(mx[mi][0], fmaxf(s[mi][ni][0], s[mi][ni][1]));
            mx[mi][1] = fmaxf(mx[mi][1], fmaxf(s[mi][ni][2], s[mi][ni][3]));
        }
    #pragma unroll
    for (int mi = 0; mi < 2; mi++)
        #pragma unroll
        for (int hf = 0; hf < 2; hf++) {
            mx[mi][hf] = fmaxf(mx[mi][hf], __shfl_xor_sync(0xffffffffu, mx[mi][hf], 1));
            mx[mi][hf] = fmaxf(mx[mi][hf], __shfl_xor_sync(0xffffffffu, mx[mi][hf], 2));
        }
    float sum[2][2] = {};
    #pragma unroll
    for (int mi = 0; mi < 2; mi++)
        #pragma unroll
        for (int ni = 0; ni < 16; ni++) {
            s[mi][ni][0] = expf(s[mi][ni][0] - mx[mi][0]);
            s[mi][ni][1] = expf(s[mi][ni][1] - mx[mi][0]);
            s[mi][ni][2] = expf(s[mi][ni][2] - mx[mi][1]);
            s[mi][ni][3] = expf(s[mi][ni][3] - mx[mi][1]);
            sum[mi][0] += s[mi][ni][0] + s[mi][ni][1];
            sum[mi][1] += s[mi][ni][2] + s[mi][ni][3];
        }
    float inv[2][2];
    #pragma unroll
    for (int mi = 0; mi < 2; mi++)
        #pragma unroll
        for (int hf = 0; hf < 2; hf++) {
            float ss = sum[mi][hf];
            ss += __shfl_xor_sync(0xffffffffu, ss, 1);
            ss += __shfl_xor_sync(0xffffffffu, ss, 2);
            inv[mi][hf] = 1.f / ss;
        }

    // ---- write P (unnormalized, tf32) to smem; warp-local rows only ----
    #pragma unroll
    for (int mi = 0; mi < 2; mi++) {
        int r0 = m0 + mi * 16 + g;
        #pragma unroll
        for (int ni = 0; ni < 16; ni++) {
            int c = ni * 8 + 2 * t;
            Ps[ r0      *APS + c    ] = to_tf32(s[mi][ni][0]);
            Ps[ r0      *APS + c + 1] = to_tf32(s[mi][ni][1]);
            Ps[(r0 + 8) *APS + c    ] = to_tf32(s[mi][ni][2]);
            Ps[(r0 + 8) *APS + c + 1] = to_tf32(s[mi][ni][3]);
        }
    }
    __syncwarp();

    // ---- O = P @ V  (M=32, N=32, K=128) ----
    float o[2][4][4] = {};
    #pragma unroll
    for (int kk = 0; kk < 128; kk += 8) {
        uint32_t afrag[2][4];
        #pragma unroll
        for (int mi = 0; mi < 2; mi++) {
            int r = m0 + mi * 16;
            afrag[mi][0] = __float_as_uint(Ps[(r + g    )*APS + kk + t    ]);
            afrag[mi][1] = __float_as_uint(Ps[(r + g + 8)*APS + kk + t    ]);
            afrag[mi][2] = __float_as_uint(Ps[(r + g    )*APS + kk + t + 4]);
            afrag[mi][3] = __float_as_uint(Ps[(r + g + 8)*APS + kk + t + 4]);
        }
        #pragma unroll
        for (int ni = 0; ni < 4; ni++) {
            int c = ni * 8;
            uint32_t b0 = __float_as_uint(VT[(c + g)*APS + kk + t    ]);
            uint32_t b1 = __float_as_uint(VT[(c + g)*APS + kk + t + 4]);
            mma8(o[0][ni], afrag[0], b0, b1);
            mma8(o[1][ni], afrag[1], b0, b1);
        }
    }

    // ---- epilogue: normalize and store ----
    #pragma unroll
    for (int mi = 0; mi < 2; mi++) {
        int r0 = m0 + mi * 16 + g;
        #pragma unroll
        for (int ni = 0; ni < 4; ni++) {
            int d = ni * 8 + 2 * t;
            *(float2*)(g_o + (size_t)(n*NP + r0    )*DD + h*32 + d) =
                make_float2(o[mi][ni][0]*inv[mi][0], o[mi][ni][1]*inv[mi][0]);
            *(float2*)(g_o + (size_t)(n*NP + r0 + 8)*DD + h*32 + d) =
                make_float2(o[mi][ni][2]*inv[mi][1], o[mi][ni][3]*inv[mi][1]);
        }
    }
}

// ---------------- mean over Np -----------------------------------------------
__global__ void k_mean()
{
    int n = blockIdx.x, d = threadIdx.x;
    float s = 0.f;
    for (int p = 0; p < NP; p++) s += g_Htemp[((size_t)n*NP + p)*DD + d];
    g_Hs[n*DD + d] = s * (1.f/128.f);
}

// ---------------- graph adjacency --------------------------------------------
__global__ void k_graph(const float* __restrict__ adj)
{
    __shared__ float k2s[CC*DK];
    __shared__ float Amat[CC*65];
    int b = blockIdx.x, c = threadIdx.x;
    for (int idx = c; idx < CC*DK; idx += 64) k2s[idx] = g_k2[(size_t)b*CC*DK + idx];
    __syncthreads();
    float qreg[DK];
    #pragma unroll
    for (int d = 0; d < DK; d++) qreg[d] = g_q2[(size_t)b*CC*DK + c*DK + d];
    for (int e = 0; e < CC; e++) {
        float a = 0.f;
        #pragma unroll
        for (int d = 0; d < DK; d++) a += qreg[d] * k2s[e*DK + d];
        Amat[c*65 + e] = tanhf(a * 0.125f) + adj[c*CC + e];
    }
    for (int e = 0; e < CC; e++) g_mask[(size_t)b*CC*CC + c*CC + e] = 0.f;
    for (int kk = 0; kk < 8; kk++) {
        float best = -INFINITY; int bi = 0;
        for (int e = 0; e < CC; e++) {
            float v = Amat[c*65 + e];
            if (v > best) { best = v; bi = e; }
        }
        if (bi != c && best != 0.f) g_mask[(size_t)b*CC*CC + c*CC + bi] = 1.f;
        Amat[c*65 + bi] = -INFINITY;
    }
}

// ---------------- fused GAT + snorm LN: CTA per (b, p) ------------------------
__global__ void k_gat(const float* __restrict__ attsrc, const float* __restrict__ attdst,
                      const float* __restrict__ gbias, const float* __restrict__ sg,
                      const float* __restrict__ sb, float* __restrict__ out)
{
    extern __shared__ float sm[];
    float* Xh  = sm;               // 8192
    float* Aw  = sm + 8192;        // 4160 (stride 65)
    float* Asv = sm + 12352;       // 64
    float* Adv = sm + 12416;       // 64
    int b = blockIdx.x >> 7, p = blockIdx.x & 127;
    int tid = threadIdx.x, w = tid >> 5, lane = tid & 31;

    float acc[8][4] = {};
    for (int h = 0; h < HS; h++) {
        __syncthreads();
        for (int idx = tid; idx < CC*FF; idx += 256) {
            int s = idx >> 7, f = idx & 127;
            Xh[idx] = g_xh[(size_t)(((b*CC + s)*NP + p))*(HS*FF) + h*FF + f];
        }
        __syncthreads();

        for (int s = w; s < CC; s += 8) {
            float vs = 0.f, vd = 0.f;
            #pragma unroll
            for (int j = 0; j < 4; j++) {
                int f = lane + 32*j;
                float xv = Xh[s*FF + f];
                vs += xv * attsrc[h*FF + f];
                vd += xv * attdst[h*FF + f];
            }
            #pragma unroll
            for (int o = 16; o; o >>= 1) {
                vs += __shfl_xor_sync(0xffffffffu, vs, o);
                vd += __shfl_xor_sync(0xffffffffu, vd, o);
            }
            if (lane == 0) { Asv[s] = vs; Adv[s] = vd; }
        }
        __syncthreads();

        #pragma unroll
        for (int i = 0; i < 8; i++) {
            int t = w*8 + i;
            float adt = Adv[t];
            float m0 = g_mask[(size_t)b*CC*CC + lane*CC + t];
            float m1 = g_mask[(size_t)b*CC*CC + (lane+32)*CC + t];
            float e0 = Asv[lane]      + adt; e0 = e0 > 0.f ? e0 : 0.2f*e0;
            float e1 = Asv[lane + 32] + adt; e1 = e1 > 0.f ? e1 : 0.2f*e1;
            float me = fmaxf(m0 > 0.5f ? e0 : GAT_NEG, m1 > 0.5f ? e1 : GAT_NEG);
            #pragma unroll
            for (int o = 16; o; o >>= 1) me = fmaxf(me, __shfl_xor_sync(0xffffffffu, me, o));
            float w0 = (m0 > 0.5f) ? expf(e0 - me) : 0.f;
            float w1 = (m1 > 0.5f) ? expf(e1 - me) : 0.f;
            float ws = w0 + w1;
            #pragma unroll
            for (int o = 16; o; o >>= 1) ws += __shfl_xor_sync(0xffffffffu, ws, o);
            float inv = ws > 0.f ? 1.f / ws : 0.f;
            Aw[lane*65 + t]      = w0 * inv;
            Aw[(lane+32)*65 + t] = w1 * inv;
        }
        __syncthreads();

        for (int s = 0; s < CC; s++) {
            float xv[4];
            #pragma unroll
            for (int j = 0; j < 4; j++) xv[j] = Xh[s*FF + lane + 32*j];
            #pragma unroll
            for (int i = 0; i < 8; i++) {
                float a = Aw[s*65 + w*8 + i];
                #pragma unroll
                for (int j = 0; j < 4; j++) acc[i][j] += a * xv[j];
            }
        }
    }

    #pragma unroll
    for (int i = 0; i < 8; i++) {
        int t = w*8 + i;
        const float* hrow = &g_Htemp[(((size_t)(b*CC + t))*NP + p)*DD];
        float v[4]; float s1 = 0.f;
        #pragma unroll
        for (int j = 0; j < 4; j++) {
            int f = lane + 32*j;
            v[j] = acc[i][j]*0.25f + gbias[f] + hrow[f];
            s1 += v[j];
        }
        #pragma unroll
        for (int o = 16; o; o >>= 1) s1 += __shfl_xor_sync(0xffffffffu, s1, o);
        float mean = s1 * (1.f/128.f);
        float s2 = 0.f;
        #pragma unroll
        for (int j = 0; j < 4; j++) { float d = v[j] - mean; s2 += d*d; }
        #pragma unroll
        for (int o = 16; o; o >>= 1) s2 += __shfl_xor_sync(0xffffffffu, s2, o);
        float inv = rsqrtf(s2 * (1.f/128.f) + 1e-5f);
        #pragma unroll
        for (int j = 0; j < 4; j++) {
            int f = lane + 32*j;
            out[(((size_t)(b*CC + t))*NP + p)*DD + f] = (v[j] - mean)*inv*sg[f] + sb[f];
        }
    }
}

// ---------------- host launch -------------------------------------------------
extern "C" void kernel_launch(void* const* d_in, const int* in_sizes, int n_in,
                              void* d_out, int out_size)
{
    const float* H_in      = (const float*)d_in[0];
    const float* static_adj= (const float*)d_in[1];
    const float* attn_in_w = (const float*)d_in[2];
    const float* attn_in_b = (const float*)d_in[3];
    const float* attn_out_w= (const float*)d_in[4];
    const float* attn_out_b= (const float*)d_in[5];
    const float* ln1_g     = (const float*)d_in[6];
    const float* ln1_b     = (const float*)d_in[7];
    const float* ln2_g     = (const float*)d_in[8];
    const float* ln2_b     = (const float*)d_in[9];
    const float* ff1_w     = (const float*)d_in[10];
    const float* ff1_b     = (const float*)d_in[11];
    const float* ff2_w     = (const float*)d_in[12];
    const float* ff2_b     = (const float*)d_in[13];
    const float* tnorm_g   = (const float*)d_in[14];
    const float* tnorm_b   = (const float*)d_in[15];
    const float* q_w       = (const float*)d_in[16];
    const float* q_b       = (const float*)d_in[17];
    const float* k_w       = (const float*)d_in[18];
    const float* k_b       = (const float*)d_in[19];
    const float* gat_w     = (const float*)d_in[20];
    const float* gat_att_src = (const float*)d_in[21];
    const float* gat_att_dst = (const float*)d_in[22];
    const float* gat_bias  = (const float*)d_in[23];
    const float* snorm_g   = (const float*)d_in[24];
    const float* snorm_b   = (const float*)d_in[25];

    float *h_, *qkv_, *o_, *x_, *ff_, *Htemp_, *xh_, *Hs_, *q2_, *k2_;
    cudaGetSymbolAddress((void**)&h_,     g_h);
    cudaGetSymbolAddress((void**)&qkv_,   g_qkv);
    cudaGetSymbolAddress((void**)&o_,     g_o);
    cudaGetSymbolAddress((void**)&x_,     g_x);
    cudaGetSymbolAddress((void**)&ff_,    g_ff);
    cudaGetSymbolAddress((void**)&Htemp_, g_Htemp);
    cudaGetSymbolAddress((void**)&xh_,    g_xh);
    cudaGetSymbolAddress((void**)&Hs_,    g_Hs);
    cudaGetSymbolAddress((void**)&q2_,    g_q2);
    cudaGetSymbolAddress((void**)&k2_,    g_k2);

    const int attn_smem = (128*APS + 32*APS) * 4;   // 84480
    const int gat_smem  = 12480 * 4;                // 49920
    cudaFuncSetAttribute(k_attn_mma, cudaFuncAttributeMaxDynamicSharedMemorySize, attn_smem);
    cudaFuncSetAttribute(k_gat,  cudaFuncAttributeMaxDynamicSharedMemorySize, gat_smem);

    // 1) h = ln1(x0)
    k_ln<<<NTOK/8, 256>>>(H_in, nullptr, ln1_g, ln1_b, h_);
    // 2) qkv = h @ Wqkv^T + b
    k_mma<<<dim3(384/TBN, NTOK/TBM), 256>>>(h_, attn_in_w, attn_in_b, nullptr, qkv_,
                                            NTOK, 384, 128, 0);
    // 3) temporal attention (tensor cores)
    k_attn_mma<<<NSEQ*HT, 128, attn_smem>>>();
    // 4) x1 = x0 + o @ Wout^T + b
    k_mma<<<dim3(128/TBN, NTOK/TBM), 256>>>(o_, attn_out_w, attn_out_b, H_in, x_,
                                            NTOK, 128, 128, 0);
    // 5) h = ln2(x1)
    k_ln<<<NTOK/8, 256>>>(x_, nullptr, ln2_g, ln2_b, h_);
    // 6) ff = relu(h @ W1^T + b1)
    k_mma<<<dim3(512/TBN, NTOK/TBM), 256>>>(h_, ff1_w, ff1_b, nullptr, ff_,
                                            NTOK, 512, 128, 1);
    // 7) x2 = x1 + ff @ W2^T + b2
    k_mma<<<dim3(128/TBN, NTOK/TBM), 256>>>(ff_, ff2_w, ff2_b, x_, x_,
                                            NTOK, 128, 512, 0);
    // 8) H_temp = ln(x0 + x2, tnorm)
    k_ln<<<NTOK/8, 256>>>(x_, H_in, tnorm_g, tnorm_b, Htemp_);
    // 9) xh = H_temp @ gat_w^T
    k_mma<<<dim3(512/TBN, NTOK/TBM), 256>>>(Htemp_, gat_w, nullptr, nullptr, xh_,
                                            NTOK, 512, 128, 0);
    // 10) Hs = mean_p(H_temp)
    k_mean<<<NSEQ, 128>>>();
    // 11) q2, k2
    k_gemm<<<dim3(1, NSEQ/BM), 256>>>(Hs_, q_w, q_b, q2_, NSEQ, 64, 128);
    k_gemm<<<dim3(1, NSEQ/BM), 256>>>(Hs_, k_w, k_b, k2_, NSEQ, 64, 128);
    // 12) adjacency / top-k / mask
    k_graph<<<BB, 64>>>(static_adj);
    // 13) fused GAT + snorm LN -> output
    k_gat<<<BB*NP, 256, gat_smem>>>(gat_att_src, gat_att_dst, gat_bias,
                                    snorm_g, snorm_b, (float*)d_out);
}